// round 15
// baseline (speedup 1.0000x reference)
#include <cuda_runtime.h>
#include <cuda_fp16.h>
#include <math.h>
#include <stdint.h>

// ---------------------------------------------------------------------------
// QBNN attention, all-fp16 tensor-core pipeline. B=2, S=2048, E=1024, H=16, hd=64.
//  0) convert: x -> fp16 ; W* -> transposed fp16 (fused 4-way)
//  1) gemm_fp16 fused: QKV = x@[Wq|Wk|Wv] + b  (one launch, N=3072)
//  2) prep: shfl-based J matmul -> Qcat(log2e)/Kcat fp16 (V stays in QKV)
//  3) flash16: 128-row q-tiles, 8 warps, 2 CTAs/SM, V via ldmatrix.trans
//  4) gemm_fp16: out = O@Wo + bo (fp32 out)
// ---------------------------------------------------------------------------

#define N_TOK   4096
#define EMB     1024
#define HEADS   16
#define HD      64
#define SEQ     2048
#define BH      32
#define LOG2E   1.4426950408889634f

// fp16 scratch arena
#define HX     0
#define HW     (HX    + N_TOK*EMB)           // 4 transposed weights
#define HQKV   (HW    + 4*EMB*EMB)           // [4096][3072]
#define HQC    (HQKV  + N_TOK*3*EMB)
#define HKC    (HQC   + BH*SEQ*128)
#define HO     (HKC   + BH*SEQ*128)
#define HTOTAL (HO    + N_TOK*EMB)
__device__ __half g_hscratch[HTOTAL];

// ---------------------------------------------------------------------------
// convert: fp32 -> fp16 elementwise
// ---------------------------------------------------------------------------
__global__ __launch_bounds__(256)
void convert_kernel(const float* __restrict__ src, __half* __restrict__ dst, int n4)
{
    int i = blockIdx.x * blockDim.x + threadIdx.x;
    if (i >= n4) return;
    float4 v = ((const float4*)src)[i];
    __half2 h0 = __floats2half2_rn(v.x, v.y);
    __half2 h1 = __floats2half2_rn(v.z, v.w);
    uint2 w;
    w.x = *(uint32_t*)&h0;
    w.y = *(uint32_t*)&h1;
    ((uint2*)dst)[i] = w;
}

// ---------------------------------------------------------------------------
// fused transpose+convert of all 4 weights: W[k][n] fp32 -> Wt[n][k] fp16
// ---------------------------------------------------------------------------
__global__ __launch_bounds__(256)
void transpose4_kernel(const float* __restrict__ W0, const float* __restrict__ W1,
                       const float* __restrict__ W2, const float* __restrict__ W3,
                       __half* __restrict__ Tbase)
{
    __shared__ float tile[32][33];
    int z  = blockIdx.z;
    const float* W = (z == 0) ? W0 : (z == 1) ? W1 : (z == 2) ? W2 : W3;
    __half* T = Tbase + (size_t)z * EMB * EMB;

    int k0 = blockIdx.y * 32;
    int n0 = blockIdx.x * 32;
    int tx = threadIdx.x & 31;
    int ty = threadIdx.x >> 5;
#pragma unroll
    for (int j = 0; j < 4; j++)
        tile[ty + j * 8][tx] = W[(size_t)(k0 + ty + j * 8) * EMB + n0 + tx];
    __syncthreads();
#pragma unroll
    for (int j = 0; j < 4; j++) {
        int n = ty + j * 8;
        T[(size_t)(n0 + n) * EMB + k0 + tx] = __float2half(tile[tx][n]);
    }
}

// ---------------------------------------------------------------------------
// helpers
// ---------------------------------------------------------------------------
#define MMA16816H(d, a0, a1, a2, a3, b0, b1)                                 \
    asm volatile(                                                            \
        "mma.sync.aligned.m16n8k16.row.col.f32.f16.f16.f32 "                 \
        "{%0,%1,%2,%3}, {%4,%5,%6,%7}, {%8,%9}, {%0,%1,%2,%3};"              \
        : "+f"(d[0]), "+f"(d[1]), "+f"(d[2]), "+f"(d[3])                     \
        : "r"(a0), "r"(a1), "r"(a2), "r"(a3), "r"(b0), "r"(b1))

#define LDSM_X4(r0, r1, r2, r3, addr)                                        \
    asm volatile("ldmatrix.sync.aligned.m8n8.x4.shared.b16 {%0,%1,%2,%3}, [%4];" \
        : "=r"(r0), "=r"(r1), "=r"(r2), "=r"(r3) : "r"(addr))

#define LDSM_X4_T(r0, r1, r2, r3, addr)                                      \
    asm volatile("ldmatrix.sync.aligned.m8n8.x4.trans.shared.b16 {%0,%1,%2,%3}, [%4];" \
        : "=r"(r0), "=r"(r1), "=r"(r2), "=r"(r3) : "r"(addr))

__device__ __forceinline__ void cp16s(uint32_t smem_dst, const void* gmem_src)
{
    asm volatile("cp.async.cg.shared.global [%0], [%1], 16;"
                 :: "r"(smem_dst), "l"(gmem_src));
}

__device__ __forceinline__ uint32_t h2exp2(uint32_t x)
{
    uint32_t r;
    asm("ex2.approx.f16x2 %0, %1;" : "=r"(r) : "r"(x));
    return r;
}

__device__ __forceinline__ float tanh_fast(float x)
{
    float r;
    asm("tanh.approx.f32 %0, %1;" : "=f"(r) : "f"(x));
    return r;
}

// ---------------------------------------------------------------------------
// Single-pass fp16 tensor-core GEMM, fused-N capable.
// ---------------------------------------------------------------------------
#define GSTAGE  32768
#define GSMEM   (3 * GSTAGE)

__global__ __launch_bounds__(256, 2)
void gemm_fp16(const __half* __restrict__ A, const __half* __restrict__ Bt,
               const float* __restrict__ b0p, const float* __restrict__ b1p,
               const float* __restrict__ b2p,
               void* __restrict__ Cout, int outN, int half_out)
{
    extern __shared__ __align__(1024) char smem[];
    const int K = 1024;
    uint32_t sbase;
    asm("{ .reg .u64 t; cvta.to.shared.u64 t, %1; cvt.u32.u64 %0, t; }"
        : "=r"(sbase) : "l"(smem));

    int tid  = threadIdx.x;
    int warp = tid >> 5;
    int lane = tid & 31;
    int wm   = warp & 1;
    int wn   = warp >> 1;
    int m0   = blockIdx.y * 128;
    int n0   = blockIdx.x * 128;

    int sec = n0 >> 10;
    const float* bias = (sec == 0) ? b0p : (sec == 1) ? b1p : b2p;
    int nloc = n0 & 1023;

    float acc[4][4][4];
#pragma unroll
    for (int mi = 0; mi < 4; mi++)
#pragma unroll
        for (int nj = 0; nj < 4; nj++)
#pragma unroll
            for (int t = 0; t < 4; t++) acc[mi][nj][t] = 0.f;

    auto issue = [&](int chunk, int stg) {
        int k0 = chunk << 6;
        const __half* Ap = A  + (size_t)m0 * K + k0;
        const __half* Bp = Bt + (size_t)n0 * K + k0;
        uint32_t aBuf = sbase + stg * GSTAGE;
        uint32_t bBuf = aBuf + 16384;
#pragma unroll
        for (int i = 0; i < 4; i++) {
            int idx = tid + i * 256;
            int r   = idx >> 3;
            int c   = idx & 7;
            uint32_t sw = (uint32_t)(r << 7) | ((uint32_t)(c ^ (r & 7)) << 4);
            cp16s(aBuf + sw, Ap + (size_t)r * K + c * 8);
            cp16s(bBuf + sw, Bp + (size_t)r * K + c * 8);
        }
        asm volatile("cp.async.commit_group;");
    };

    issue(0, 0);
    issue(1, 1);

    int lm  = lane >> 3;
    int lr  = lane & 7;

    for (int t = 0; t < 16; t++) {
        int stg = t % 3;
        if (t < 15) asm volatile("cp.async.wait_group 1;");
        else        asm volatile("cp.async.wait_group 0;");
        __syncthreads();

        uint32_t aBuf = sbase + stg * GSTAGE;
        uint32_t bBuf = aBuf + 16384;

#pragma unroll
        for (int kk = 0; kk < 64; kk += 16) {
            int kc = kk >> 3;
            uint32_t af[4][4];
#pragma unroll
            for (int mi = 0; mi < 4; mi++) {
                int row = wm * 64 + mi * 16 + (lm & 1) * 8 + lr;
                int ch  = kc + (lm >> 1);
                uint32_t ad = aBuf + (uint32_t)(row << 7) + ((uint32_t)(ch ^ (row & 7)) << 4);
                LDSM_X4(af[mi][0], af[mi][1], af[mi][2], af[mi][3], ad);
            }
            uint32_t bf_[4][2];
#pragma unroll
            for (int njp = 0; njp < 2; njp++) {
                int row = wn * 32 + njp * 16 + (lm >> 1) * 8 + lr;
                int ch  = kc + (lm & 1);
                uint32_t bd = bBuf + (uint32_t)(row << 7) + ((uint32_t)(ch ^ (row & 7)) << 4);
                LDSM_X4(bf_[njp * 2][0], bf_[njp * 2][1],
                        bf_[njp * 2 + 1][0], bf_[njp * 2 + 1][1], bd);
            }
#pragma unroll
            for (int mi = 0; mi < 4; mi++)
#pragma unroll
                for (int nj = 0; nj < 4; nj++)
                    MMA16816H(acc[mi][nj], af[mi][0], af[mi][1], af[mi][2], af[mi][3],
                              bf_[nj][0], bf_[nj][1]);
        }

        if (t + 2 < 16) issue(t + 2, (t + 2) % 3);
    }

    int g  = lane >> 2;
    int tq = lane & 3;
#pragma unroll
    for (int mi = 0; mi < 4; mi++) {
        size_t r0 = (size_t)(m0 + wm * 64 + mi * 16 + g);
        size_t r1 = r0 + 8;
#pragma unroll
        for (int nj = 0; nj < 4; nj++) {
            int cl = wn * 32 + nj * 8 + tq * 2;
            float b0 = bias[nloc + cl], b1 = bias[nloc + cl + 1];
            int c  = n0 + cl;
            float v00 = acc[mi][nj][0] + b0, v01 = acc[mi][nj][1] + b1;
            float v10 = acc[mi][nj][2] + b0, v11 = acc[mi][nj][3] + b1;
            if (half_out) {
                __half* C = (__half*)Cout;
                *(__half2*)&C[r0 * outN + c] = __floats2half2_rn(v00, v01);
                *(__half2*)&C[r1 * outN + c] = __floats2half2_rn(v10, v11);
            } else {
                float* C = (float*)Cout;
                *(float2*)&C[r0 * outN + c] = make_float2(v00, v01);
                *(float2*)&C[r1 * outN + c] = make_float2(v10, v11);
            }
        }
    }
}

// ---------------------------------------------------------------------------
// prep: shfl-based J matmul. Block (32 lanes, 16 tokens); each thread owns
// dims d and d+32 of one (token, head); tanh(q) exchanged via warp shuffles.
// ---------------------------------------------------------------------------
__global__ __launch_bounds__(512)
void prep_kernel(const __half* __restrict__ QKV, const float* __restrict__ J,
                 const float* __restrict__ lamp,
                 __half* __restrict__ Qc, __half* __restrict__ Kc)
{
    __shared__ float Js[4096];

    int h   = blockIdx.y;
    int d   = threadIdx.x;           // 0..31
    int ty  = threadIdx.y;           // 0..15
    int tid = ty * 32 + d;

    for (int i = tid; i < 4096; i += 512) Js[i] = J[h * 4096 + i];

    int tok = blockIdx.x * 16 + ty;
    int b   = tok >> 11;
    int s   = tok & 2047;
    int bh  = (b << 4) + h;

    const __half* row = QKV + (size_t)tok * 3072 + h * HD + d;
    float q0 = __half2float(row[0]);
    float q1 = __half2float(row[32]);
    float k0 = __half2float(row[1024]);
    float k1 = __half2float(row[1056]);
    float qn0 = tanh_fast(q0);
    float qn1 = tanh_fast(q1);
    __syncthreads();

    float acc0 = 0.f, acc1 = 0.f;
#pragma unroll
    for (int dd = 0; dd < 32; dd++) {
        float a = __shfl_sync(0xffffffffu, qn0, dd);
        acc0 += a * Js[dd * 64 + d];
        acc1 += a * Js[dd * 64 + d + 32];
    }
#pragma unroll
    for (int dd = 0; dd < 32; dd++) {
        float a = __shfl_sync(0xffffffffu, qn1, dd);
        acc0 += a * Js[(dd + 32) * 64 + d];
        acc1 += a * Js[(dd + 32) * 64 + d + 32];
    }

    float lam = lamp[0];
    size_t base = (size_t)bh * SEQ + s;
    Qc[base * 128 + d]       = __float2half(q0 * 0.125f * LOG2E);
    Qc[base * 128 + d + 32]  = __float2half(q1 * 0.125f * LOG2E);
    Qc[base * 128 + 64 + d]  = __float2half(lam * acc0 * LOG2E);
    Qc[base * 128 + 96 + d]  = __float2half(lam * acc1 * LOG2E);
    Kc[base * 128 + d]       = __float2half(k0);
    Kc[base * 128 + d + 32]  = __float2half(k1);
    Kc[base * 128 + 64 + d]  = __float2half(tanh_fast(k0));
    Kc[base * 128 + 96 + d]  = __float2half(tanh_fast(k1));
}

// ---------------------------------------------------------------------------
// flash16: 128-row q-tiles, 8 warps, 2-stage KV, 2 CTAs/SM.
// Q fragments reloaded per k-tile from smem (frees 32 regs for occupancy).
// ---------------------------------------------------------------------------
#define FLQ_BYTES  32768
#define FLSTAGE    24576
#define FL16_SMEM  (FLQ_BYTES + 2 * FLSTAGE)   // 80KB -> 2 CTAs/SM

__global__ __launch_bounds__(256, 2)
void flash16_kernel(const __half* __restrict__ Qc, const __half* __restrict__ Kc,
                    const __half* __restrict__ QKV, __half* __restrict__ O)
{
    extern __shared__ __align__(1024) char smem[];
    uint32_t sbase;
    asm("{ .reg .u64 t; cvta.to.shared.u64 t, %1; cvt.u32.u64 %0, t; }"
        : "=r"(sbase) : "l"(smem));

    int tid  = threadIdx.x;
    int w    = tid >> 5;
    int lane = tid & 31;
    int lm   = lane >> 3;
    int lr   = lane & 7;
    int g    = lane >> 2;
    int tq   = lane & 3;

    int bh    = blockIdx.y;
    int b     = bh >> 4;
    int h     = bh & 15;
    int qtile = (int)gridDim.x - 1 - (int)blockIdx.x;
    int qt0   = qtile * 128;
    int nkt   = 2 * qtile + 2;

    const __half* Qg = Qc + ((size_t)bh * SEQ + qt0) * 128;
#pragma unroll
    for (int i = 0; i < 8; i++) {
        int idx = tid + i * 256;
        int r   = idx >> 4;
        int ch  = idx & 15;
        uint32_t dst = sbase + (uint32_t)(ch >> 3) * 16384
                     + (uint32_t)(r << 7) + ((uint32_t)((ch & 7) ^ (r & 7)) << 4);
        cp16s(dst, Qg + (size_t)r * 128 + ch * 8);
    }
    asm volatile("cp.async.commit_group;");

    auto issueKV = [&](int kt, int s) {
        uint32_t kb = sbase + FLQ_BYTES + (uint32_t)s * FLSTAGE;
        uint32_t vb = kb + 16384;
        const __half* Kg = Kc + ((size_t)bh * SEQ + kt * 64) * 128;
        const __half* Vg = QKV + (size_t)(b * SEQ + kt * 64) * 3072 + 2048 + h * 64;
#pragma unroll
        for (int i = 0; i < 4; i++) {
            int idx = tid + i * 256;
            int r   = idx >> 4;
            int ch  = idx & 15;
            uint32_t dst = kb + (uint32_t)(ch >> 3) * 8192
                         + (uint32_t)(r << 7) + ((uint32_t)((ch & 7) ^ (r & 7)) << 4);
            cp16s(dst, Kg + (size_t)r * 128 + ch * 8);
        }
#pragma unroll
        for (int i = 0; i < 2; i++) {
            int idx = tid + i * 256;
            int r   = idx >> 3;
            int c   = idx & 7;
            uint32_t dst = vb + (uint32_t)(r << 7) + ((uint32_t)(c ^ (r & 7)) << 4);
            cp16s(dst, Vg + (size_t)r * 3072 + c * 8);
        }
        asm volatile("cp.async.commit_group;");
    };

    issueKV(0, 0);
    issueKV(1, 1);

    float oacc[8][4];
#pragma unroll
    for (int nt = 0; nt < 8; nt++)
#pragma unroll
        for (int t = 0; t < 4; t++) oacc[nt][t] = 0.f;
    float mrow[2] = {-1e30f, -1e30f};
    float lrow[2] = {0.f, 0.f};

    int qrow0 = qt0 + w * 16;
    int r0g   = qrow0 + g;

    for (int kt = 0; kt < nkt; kt++) {
        int s_ = kt & 1;
        if (kt + 1 < nkt) asm volatile("cp.async.wait_group 1;");
        else              asm volatile("cp.async.wait_group 0;");
        __syncthreads();

        uint32_t kb = sbase + FLQ_BYTES + (uint32_t)s_ * FLSTAGE;
        uint32_t vb = kb + 16384;

        float sacc[8][4];
#pragma unroll
        for (int nt = 0; nt < 8; nt++)
#pragma unroll
            for (int t = 0; t < 4; t++) sacc[nt][t] = 0.f;

        // S = Qcat @ Kcat^T  (Q fragments reloaded per tile from resident smem)
#pragma unroll
        for (int ks = 0; ks < 8; ks++) {
            int half = ks >> 2;
            int qkc  = (ks & 3) * 2 + (lm >> 1);
            int qrow = w * 16 + (lm & 1) * 8 + lr;
            uint32_t qad = sbase + (uint32_t)half * 16384
                         + (uint32_t)(qrow << 7) + ((uint32_t)(qkc ^ (qrow & 7)) << 4);
            uint32_t q0, q1, q2, q3;
            LDSM_X4(q0, q1, q2, q3, qad);

            int kc = (ks & 3) * 2 + (lm & 1);
            uint32_t kf[8][2];
#pragma unroll
            for (int nb = 0; nb < 4; nb++) {
                int row = nb * 16 + (lm >> 1) * 8 + lr;
                uint32_t ad = kb + (uint32_t)half * 8192
                            + (uint32_t)(row << 7) + ((uint32_t)(kc ^ (row & 7)) << 4);
                LDSM_X4(kf[nb * 2][0], kf[nb * 2][1],
                        kf[nb * 2 + 1][0], kf[nb * 2 + 1][1], ad);
            }
#pragma unroll
            for (int nt = 0; nt < 8; nt++)
                MMA16816H(sacc[nt], q0, q1, q2, q3, kf[nt][0], kf[nt][1]);
        }

        if (kt * 64 + 63 > qrow0) {
#pragma unroll
            for (int nt = 0; nt < 8; nt++) {
                int c0 = kt * 64 + nt * 8 + 2 * tq;
                if (c0     > r0g)     sacc[nt][0] = -1e30f;
                if (c0 + 1 > r0g)     sacc[nt][1] = -1e30f;
                if (c0     > r0g + 8) sacc[nt][2] = -1e30f;
                if (c0 + 1 > r0g + 8) sacc[nt][3] = -1e30f;
            }
        }

        float tm0 = -1e30f, tm1 = -1e30f;
#pragma unroll
        for (int nt = 0; nt < 8; nt++) {
            tm0 = fmaxf(tm0, fmaxf(sacc[nt][0], sacc[nt][1]));
            tm1 = fmaxf(tm1, fmaxf(sacc[nt][2], sacc[nt][3]));
        }
        tm0 = fmaxf(tm0, __shfl_xor_sync(0xffffffffu, tm0, 1));
        tm0 = fmaxf(tm0, __shfl_xor_sync(0xffffffffu, tm0, 2));
        tm1 = fmaxf(tm1, __shfl_xor_sync(0xffffffffu, tm1, 1));
        tm1 = fmaxf(tm1, __shfl_xor_sync(0xffffffffu, tm1, 2));

        float mnew0 = fmaxf(mrow[0], tm0);
        float mnew1 = fmaxf(mrow[1], tm1);
        float corr0 = exp2f(mrow[0] - mnew0);
        float corr1 = exp2f(mrow[1] - mnew1);
        mrow[0] = mnew0;
        mrow[1] = mnew1;
#pragma unroll
        for (int nt = 0; nt < 8; nt++) {
            oacc[nt][0] *= corr0; oacc[nt][1] *= corr0;
            oacc[nt][2] *= corr1; oacc[nt][3] *= corr1;
        }

        uint32_t pf[4][4];
        float ps0 = 0.f, ps1 = 0.f;
#pragma unroll
        for (int nt = 0; nt < 8; nt++) {
            __half2 d0 = __floats2half2_rn(sacc[nt][0] - mnew0, sacc[nt][1] - mnew0);
            __half2 d1 = __floats2half2_rn(sacc[nt][2] - mnew1, sacc[nt][3] - mnew1);
            uint32_t p0 = h2exp2(*(uint32_t*)&d0);
            uint32_t p1 = h2exp2(*(uint32_t*)&d1);
            float2 f0 = __half22float2(*(__half2*)&p0);
            float2 f1 = __half22float2(*(__half2*)&p1);
            ps0 += f0.x + f0.y;
            ps1 += f1.x + f1.y;
            pf[nt >> 1][(nt & 1) * 2]     = p0;
            pf[nt >> 1][(nt & 1) * 2 + 1] = p1;
        }
        ps0 += __shfl_xor_sync(0xffffffffu, ps0, 1);
        ps0 += __shfl_xor_sync(0xffffffffu, ps0, 2);
        ps1 += __shfl_xor_sync(0xffffffffu, ps1, 1);
        ps1 += __shfl_xor_sync(0xffffffffu, ps1, 2);
        lrow[0] = lrow[0] * corr0 + ps0;
        lrow[1] = lrow[1] * corr1 + ps1;

        // O += P @ V : V tile [s][dv]; trans-ldmatrix -> B fragments
#pragma unroll
        for (int kc16 = 0; kc16 < 4; kc16++) {
            uint32_t vf[8][2];
#pragma unroll
            for (int nb = 0; nb < 4; nb++) {
                int srow = kc16 * 16 + (lm & 1) * 8 + lr;
                int ch   = nb * 2 + (lm >> 1);
                uint32_t ad = vb + (uint32_t)(srow << 7)
                            + ((uint32_t)(ch ^ (srow & 7)) << 4);
                LDSM_X4_T(vf[nb * 2][0], vf[nb * 2][1],
                          vf[nb * 2 + 1][0], vf[nb * 2 + 1][1], ad);
            }
#pragma unroll
            for (int nt = 0; nt < 8; nt++)
                MMA16816H(oacc[nt], pf[kc16][0], pf[kc16][1], pf[kc16][2], pf[kc16][3],
                          vf[nt][0], vf[nt][1]);
        }

        __syncthreads();
        if (kt + 2 < nkt) issueKV(kt + 2, s_);
    }

    float inv0 = 1.0f / lrow[0];
    float inv1 = 1.0f / lrow[1];
    size_t rt0 = (size_t)(b * SEQ + qt0 + w * 16 + g);
    __half* O0 = O + rt0 * EMB + h * 64;
    __half* O1 = O0 + (size_t)8 * EMB;
#pragma unroll
    for (int nt = 0; nt < 8; nt++) {
        int c = nt * 8 + 2 * tq;
        *(__half2*)&O0[c] = __floats2half2_rn(oacc[nt][0] * inv0, oacc[nt][1] * inv0);
        *(__half2*)&O1[c] = __floats2half2_rn(oacc[nt][2] * inv1, oacc[nt][3] * inv1);
    }
}

// ---------------------------------------------------------------------------
// launch
// ---------------------------------------------------------------------------
extern "C" void kernel_launch(void* const* d_in, const int* in_sizes, int n_in,
                              void* d_out, int out_size)
{
    const float* x   = (const float*)d_in[0];
    const float* Wq  = (const float*)d_in[1];
    const float* bq  = (const float*)d_in[2];
    const float* Wk  = (const float*)d_in[3];
    const float* bk  = (const float*)d_in[4];
    const float* Wv  = (const float*)d_in[5];
    const float* bv  = (const float*)d_in[6];
    const float* Wo  = (const float*)d_in[7];
    const float* bo  = (const float*)d_in[8];
    const float* J   = (const float*)d_in[9];
    const float* lam = (const float*)d_in[10];
    float* out = (float*)d_out;

    void* p = nullptr;
    cudaGetSymbolAddress(&p, g_hscratch);
    __half* hs    = (__half*)p;
    __half* x16   = hs + HX;
    __half* w16   = hs + HW;
    __half* qkv16 = hs + HQKV;
    __half* qc    = hs + HQC;
    __half* kc    = hs + HKC;
    __half* o16   = hs + HO;

    const int WSZ = EMB * EMB;
    __half* wo16 = w16 + 3 * WSZ;

    convert_kernel<<<(N_TOK * EMB / 4 + 255) / 256, 256>>>(x, x16, N_TOK * EMB / 4);
    dim3 tg(32, 32, 4), tb(256);
    transpose4_kernel<<<tg, tb>>>(Wq, Wk, Wv, Wo, w16);

    cudaFuncSetAttribute(gemm_fp16, cudaFuncAttributeMaxDynamicSharedMemorySize, GSMEM);
    gemm_fp16<<<dim3(24, 32), 256, GSMEM>>>(x16, w16, bq, bk, bv, qkv16, 3072, 1);

    dim3 prep_grid(N_TOK / 16, HEADS), prep_blk(32, 16);
    prep_kernel<<<prep_grid, prep_blk>>>(qkv16, J, lam, qc, kc);

    cudaFuncSetAttribute(flash16_kernel, cudaFuncAttributeMaxDynamicSharedMemorySize,
                         FL16_SMEM);
    dim3 fl_grid(SEQ / 128, BH);
    flash16_kernel<<<fl_grid, 256, FL16_SMEM>>>(qc, kc, qkv16, o16);

    gemm_fp16<<<dim3(8, 32), 256, GSMEM>>>(o16, wo16, bo, bo, bo, out, 1024, 0);
}

// round 16
// speedup vs baseline: 1.2344x; 1.2344x over previous
#include <cuda_runtime.h>
#include <cuda_fp16.h>
#include <math.h>
#include <stdint.h>

// ---------------------------------------------------------------------------
// QBNN attention, all-fp16 tensor-core pipeline. B=2, S=2048, E=1024, H=16, hd=64.
//  0) convert: x -> fp16 ; W* -> transposed fp16 ; J -> transposed fp16
//  1) gemm_fp16 fused: QKV = x@[Wq|Wk|Wv] + b  (one launch, N=3072)
//  2) prep_elem: Qc[0:64], Kc, tQ=tanh(Q) fp16   (pure elementwise)
//     delta_gemm: Qc[64:128] = lam*log2e * (tQ @ J)  on tensor cores
//  3) flash16 (R12-proven): 128-row q-tiles, 3-stage KV, V from QKV (trans)
//  4) gemm_fp16: out = O@Wo + bo (fp32 out)
// ---------------------------------------------------------------------------

#define N_TOK   4096
#define EMB     1024
#define HEADS   16
#define HD      64
#define SEQ     2048
#define BH      32
#define LOG2E   1.4426950408889634f

// fp16 scratch arena
#define HX     0
#define HW     (HX    + N_TOK*EMB)           // 4 transposed weights
#define HQKV   (HW    + 4*EMB*EMB)           // [4096][3072]
#define HQC    (HQKV  + N_TOK*3*EMB)
#define HKC    (HQC   + BH*SEQ*128)
#define HTQ    (HKC   + BH*SEQ*128)          // tanh(Q) [bh][s][64]
#define HJT    (HTQ   + BH*SEQ*64)           // J^T fp16 [h][d][dd]
#define HO     (HJT   + HEADS*64*64)
#define HTOTAL (HO    + N_TOK*EMB)
__device__ __half g_hscratch[HTOTAL];

// ---------------------------------------------------------------------------
// convert: fp32 -> fp16 elementwise
// ---------------------------------------------------------------------------
__global__ __launch_bounds__(256)
void convert_kernel(const float* __restrict__ src, __half* __restrict__ dst, int n4)
{
    int i = blockIdx.x * blockDim.x + threadIdx.x;
    if (i >= n4) return;
    float4 v = ((const float4*)src)[i];
    __half2 h0 = __floats2half2_rn(v.x, v.y);
    __half2 h1 = __floats2half2_rn(v.z, v.w);
    uint2 w;
    w.x = *(uint32_t*)&h0;
    w.y = *(uint32_t*)&h1;
    ((uint2*)dst)[i] = w;
}

// ---------------------------------------------------------------------------
// fused transpose+convert of all 4 weights: W[k][n] fp32 -> Wt[n][k] fp16
// ---------------------------------------------------------------------------
__global__ __launch_bounds__(256)
void transpose4_kernel(const float* __restrict__ W0, const float* __restrict__ W1,
                       const float* __restrict__ W2, const float* __restrict__ W3,
                       __half* __restrict__ Tbase)
{
    __shared__ float tile[32][33];
    int z  = blockIdx.z;
    const float* W = (z == 0) ? W0 : (z == 1) ? W1 : (z == 2) ? W2 : W3;
    __half* T = Tbase + (size_t)z * EMB * EMB;

    int k0 = blockIdx.y * 32;
    int n0 = blockIdx.x * 32;
    int tx = threadIdx.x & 31;
    int ty = threadIdx.x >> 5;
#pragma unroll
    for (int j = 0; j < 4; j++)
        tile[ty + j * 8][tx] = W[(size_t)(k0 + ty + j * 8) * EMB + n0 + tx];
    __syncthreads();
#pragma unroll
    for (int j = 0; j < 4; j++) {
        int n = ty + j * 8;
        T[(size_t)(n0 + n) * EMB + k0 + tx] = __float2half(tile[tx][n]);
    }
}

// ---------------------------------------------------------------------------
// Jt: J[h][dd][d] fp32 -> Jt[h][d][dd] fp16
// ---------------------------------------------------------------------------
__global__ __launch_bounds__(256)
void jt_kernel(const float* __restrict__ J, __half* __restrict__ Jt)
{
    __shared__ float t[32][33];
    int h   = blockIdx.z;
    int dd0 = blockIdx.y * 32;
    int d0  = blockIdx.x * 32;
    int tx  = threadIdx.x & 31;
    int ty  = threadIdx.x >> 5;
#pragma unroll
    for (int j = 0; j < 4; j++)
        t[ty + j * 8][tx] = J[h * 4096 + (dd0 + ty + j * 8) * 64 + d0 + tx];
    __syncthreads();
#pragma unroll
    for (int j = 0; j < 4; j++) {
        int d = ty + j * 8;
        Jt[h * 4096 + (d0 + d) * 64 + dd0 + tx] = __float2half(t[tx][d]);
    }
}

// ---------------------------------------------------------------------------
// helpers
// ---------------------------------------------------------------------------
#define MMA16816H(d, a0, a1, a2, a3, b0, b1)                                 \
    asm volatile(                                                            \
        "mma.sync.aligned.m16n8k16.row.col.f32.f16.f16.f32 "                 \
        "{%0,%1,%2,%3}, {%4,%5,%6,%7}, {%8,%9}, {%0,%1,%2,%3};"              \
        : "+f"(d[0]), "+f"(d[1]), "+f"(d[2]), "+f"(d[3])                     \
        : "r"(a0), "r"(a1), "r"(a2), "r"(a3), "r"(b0), "r"(b1))

#define LDSM_X4(r0, r1, r2, r3, addr)                                        \
    asm volatile("ldmatrix.sync.aligned.m8n8.x4.shared.b16 {%0,%1,%2,%3}, [%4];" \
        : "=r"(r0), "=r"(r1), "=r"(r2), "=r"(r3) : "r"(addr))

#define LDSM_X4_T(r0, r1, r2, r3, addr)                                      \
    asm volatile("ldmatrix.sync.aligned.m8n8.x4.trans.shared.b16 {%0,%1,%2,%3}, [%4];" \
        : "=r"(r0), "=r"(r1), "=r"(r2), "=r"(r3) : "r"(addr))

__device__ __forceinline__ void cp16s(uint32_t smem_dst, const void* gmem_src)
{
    asm volatile("cp.async.cg.shared.global [%0], [%1], 16;"
                 :: "r"(smem_dst), "l"(gmem_src));
}

__device__ __forceinline__ uint32_t h2exp2(uint32_t x)
{
    uint32_t r;
    asm("ex2.approx.f16x2 %0, %1;" : "=r"(r) : "r"(x));
    return r;
}

__device__ __forceinline__ float tanh_fast(float x)
{
    float r;
    asm("tanh.approx.f32 %0, %1;" : "=f"(r) : "f"(x));
    return r;
}

// ---------------------------------------------------------------------------
// Single-pass fp16 tensor-core GEMM, fused-N capable.
// ---------------------------------------------------------------------------
#define GSTAGE  32768
#define GSMEM   (3 * GSTAGE)

__global__ __launch_bounds__(256, 2)
void gemm_fp16(const __half* __restrict__ A, const __half* __restrict__ Bt,
               const float* __restrict__ b0p, const float* __restrict__ b1p,
               const float* __restrict__ b2p,
               void* __restrict__ Cout, int outN, int half_out)
{
    extern __shared__ __align__(1024) char smem[];
    const int K = 1024;
    uint32_t sbase;
    asm("{ .reg .u64 t; cvta.to.shared.u64 t, %1; cvt.u32.u64 %0, t; }"
        : "=r"(sbase) : "l"(smem));

    int tid  = threadIdx.x;
    int warp = tid >> 5;
    int lane = tid & 31;
    int wm   = warp & 1;
    int wn   = warp >> 1;
    int m0   = blockIdx.y * 128;
    int n0   = blockIdx.x * 128;

    int sec = n0 >> 10;
    const float* bias = (sec == 0) ? b0p : (sec == 1) ? b1p : b2p;
    int nloc = n0 & 1023;

    float acc[4][4][4];
#pragma unroll
    for (int mi = 0; mi < 4; mi++)
#pragma unroll
        for (int nj = 0; nj < 4; nj++)
#pragma unroll
            for (int t = 0; t < 4; t++) acc[mi][nj][t] = 0.f;

    auto issue = [&](int chunk, int stg) {
        int k0 = chunk << 6;
        const __half* Ap = A  + (size_t)m0 * K + k0;
        const __half* Bp = Bt + (size_t)n0 * K + k0;
        uint32_t aBuf = sbase + stg * GSTAGE;
        uint32_t bBuf = aBuf + 16384;
#pragma unroll
        for (int i = 0; i < 4; i++) {
            int idx = tid + i * 256;
            int r   = idx >> 3;
            int c   = idx & 7;
            uint32_t sw = (uint32_t)(r << 7) | ((uint32_t)(c ^ (r & 7)) << 4);
            cp16s(aBuf + sw, Ap + (size_t)r * K + c * 8);
            cp16s(bBuf + sw, Bp + (size_t)r * K + c * 8);
        }
        asm volatile("cp.async.commit_group;");
    };

    issue(0, 0);
    issue(1, 1);

    int lm  = lane >> 3;
    int lr  = lane & 7;

    for (int t = 0; t < 16; t++) {
        int stg = t % 3;
        if (t < 15) asm volatile("cp.async.wait_group 1;");
        else        asm volatile("cp.async.wait_group 0;");
        __syncthreads();

        uint32_t aBuf = sbase + stg * GSTAGE;
        uint32_t bBuf = aBuf + 16384;

#pragma unroll
        for (int kk = 0; kk < 64; kk += 16) {
            int kc = kk >> 3;
            uint32_t af[4][4];
#pragma unroll
            for (int mi = 0; mi < 4; mi++) {
                int row = wm * 64 + mi * 16 + (lm & 1) * 8 + lr;
                int ch  = kc + (lm >> 1);
                uint32_t ad = aBuf + (uint32_t)(row << 7) + ((uint32_t)(ch ^ (row & 7)) << 4);
                LDSM_X4(af[mi][0], af[mi][1], af[mi][2], af[mi][3], ad);
            }
            uint32_t bf_[4][2];
#pragma unroll
            for (int njp = 0; njp < 2; njp++) {
                int row = wn * 32 + njp * 16 + (lm >> 1) * 8 + lr;
                int ch  = kc + (lm & 1);
                uint32_t bd = bBuf + (uint32_t)(row << 7) + ((uint32_t)(ch ^ (row & 7)) << 4);
                LDSM_X4(bf_[njp * 2][0], bf_[njp * 2][1],
                        bf_[njp * 2 + 1][0], bf_[njp * 2 + 1][1], bd);
            }
#pragma unroll
            for (int mi = 0; mi < 4; mi++)
#pragma unroll
                for (int nj = 0; nj < 4; nj++)
                    MMA16816H(acc[mi][nj], af[mi][0], af[mi][1], af[mi][2], af[mi][3],
                              bf_[nj][0], bf_[nj][1]);
        }

        if (t + 2 < 16) issue(t + 2, (t + 2) % 3);
    }

    int g  = lane >> 2;
    int tq = lane & 3;
#pragma unroll
    for (int mi = 0; mi < 4; mi++) {
        size_t r0 = (size_t)(m0 + wm * 64 + mi * 16 + g);
        size_t r1 = r0 + 8;
#pragma unroll
        for (int nj = 0; nj < 4; nj++) {
            int cl = wn * 32 + nj * 8 + tq * 2;
            float b0 = bias[nloc + cl], b1 = bias[nloc + cl + 1];
            int c  = n0 + cl;
            float v00 = acc[mi][nj][0] + b0, v01 = acc[mi][nj][1] + b1;
            float v10 = acc[mi][nj][2] + b0, v11 = acc[mi][nj][3] + b1;
            if (half_out) {
                __half* C = (__half*)Cout;
                *(__half2*)&C[r0 * outN + c] = __floats2half2_rn(v00, v01);
                *(__half2*)&C[r1 * outN + c] = __floats2half2_rn(v10, v11);
            } else {
                float* C = (float*)Cout;
                *(float2*)&C[r0 * outN + c] = make_float2(v00, v01);
                *(float2*)&C[r1 * outN + c] = make_float2(v10, v11);
            }
        }
    }
}

// ---------------------------------------------------------------------------
// prep_elem: pure elementwise pass (half2). Writes Qc[0:64], Kc, tQ.
// ---------------------------------------------------------------------------
__global__ __launch_bounds__(256)
void prep_elem_kernel(const __half* __restrict__ QKV,
                      __half* __restrict__ Qc, __half* __restrict__ Kc,
                      __half* __restrict__ tQ)
{
    int idx = blockIdx.x * 256 + threadIdx.x;      // 0 .. N_TOK*512-1
    int tok = idx >> 9;
    int e2  = idx & 511;
    int e   = e2 << 1;
    int h   = e >> 6;
    int d   = e & 63;
    int b   = tok >> 11;
    int s   = tok & 2047;
    int bh  = (b << 4) + h;

    const __half2* row = (const __half2*)(QKV + (size_t)tok * 3072);
    float2 q = __half22float2(row[e2]);
    __half2 kh = row[512 + e2];
    float2 k = __half22float2(kh);

    size_t base = ((size_t)bh * SEQ + s) * 128;
    *(__half2*)&Qc[base + d] =
        __floats2half2_rn(q.x * 0.125f * LOG2E, q.y * 0.125f * LOG2E);
    *(__half2*)&Kc[base + d] = kh;
    *(__half2*)&Kc[base + 64 + d] =
        __floats2half2_rn(tanh_fast(k.x), tanh_fast(k.y));
    *(__half2*)&tQ[((size_t)bh * SEQ + s) * 64 + d] =
        __floats2half2_rn(tanh_fast(q.x), tanh_fast(q.y));
}

// ---------------------------------------------------------------------------
// delta_gemm: Qc[.., 64:128] = lam*log2e * (tQ @ J) per (bh, 128-row tile).
// A = tQ rows [s][64] (128B rows, swizzled), B = Jt [d][dd] (col-major).
// ---------------------------------------------------------------------------
__global__ __launch_bounds__(256)
void delta_gemm_kernel(const __half* __restrict__ tQ, const __half* __restrict__ Jt,
                       const float* __restrict__ lamp, __half* __restrict__ Qc)
{
    __shared__ __align__(1024) __half sA[128 * 64];   // 16KB
    __shared__ __align__(1024) __half sB[64 * 64];    // 8KB

    uint32_t aBuf, bBuf;
    asm("{ .reg .u64 t; cvta.to.shared.u64 t, %1; cvt.u32.u64 %0, t; }"
        : "=r"(aBuf) : "l"(sA));
    asm("{ .reg .u64 t; cvta.to.shared.u64 t, %1; cvt.u32.u64 %0, t; }"
        : "=r"(bBuf) : "l"(sB));

    int tid  = threadIdx.x;
    int w    = tid >> 5;
    int lane = tid & 31;
    int lm   = lane >> 3;
    int lr   = lane & 7;
    int g    = lane >> 2;
    int tq   = lane & 3;

    int bh  = blockIdx.y;
    int h   = bh & 15;
    int qt0 = blockIdx.x * 128;

    const __half* Ag = tQ + ((size_t)bh * SEQ + qt0) * 64;
    const __half* Bg = Jt + (size_t)h * 4096;

    // load A: 128 rows x 8 chunks = 1024
#pragma unroll
    for (int i = 0; i < 4; i++) {
        int idx = tid + i * 256;
        int r   = idx >> 3;
        int c   = idx & 7;
        uint32_t dst = aBuf + (uint32_t)(r << 7) + ((uint32_t)(c ^ (r & 7)) << 4);
        cp16s(dst, Ag + (size_t)r * 64 + c * 8);
    }
    // load B: 64 rows x 8 chunks = 512
#pragma unroll
    for (int i = 0; i < 2; i++) {
        int idx = tid + i * 256;
        int r   = idx >> 3;
        int c   = idx & 7;
        uint32_t dst = bBuf + (uint32_t)(r << 7) + ((uint32_t)(c ^ (r & 7)) << 4);
        cp16s(dst, Bg + (size_t)r * 64 + c * 8);
    }
    asm volatile("cp.async.commit_group;");
    asm volatile("cp.async.wait_group 0;");
    __syncthreads();

    float acc[8][4];
#pragma unroll
    for (int nt = 0; nt < 8; nt++)
#pragma unroll
        for (int t = 0; t < 4; t++) acc[nt][t] = 0.f;

#pragma unroll
    for (int ks = 0; ks < 4; ks++) {
        // A fragment: rows w*16..+15, k-chunk ks*2 + (lm>>1)
        int arow = w * 16 + (lm & 1) * 8 + lr;
        int ach  = ks * 2 + (lm >> 1);
        uint32_t aad = aBuf + (uint32_t)(arow << 7) + ((uint32_t)(ach ^ (arow & 7)) << 4);
        uint32_t a0, a1, a2, a3;
        LDSM_X4(a0, a1, a2, a3, aad);

        // B fragments: Jt rows = output d, chunk = k
        int bch = ks * 2 + (lm & 1);
        uint32_t bf_[8][2];
#pragma unroll
        for (int nb = 0; nb < 4; nb++) {
            int brow = nb * 16 + (lm >> 1) * 8 + lr;
            uint32_t bad = bBuf + (uint32_t)(brow << 7) + ((uint32_t)(bch ^ (brow & 7)) << 4);
            LDSM_X4(bf_[nb * 2][0], bf_[nb * 2][1],
                    bf_[nb * 2 + 1][0], bf_[nb * 2 + 1][1], bad);
        }
#pragma unroll
        for (int nt = 0; nt < 8; nt++)
            MMA16816H(acc[nt], a0, a1, a2, a3, bf_[nt][0], bf_[nt][1]);
    }

    float scale = lamp[0] * LOG2E;
    size_t r0 = (size_t)bh * SEQ + qt0 + w * 16 + g;
    __half* Q0 = Qc + r0 * 128 + 64;
    __half* Q1 = Q0 + (size_t)8 * 128;
#pragma unroll
    for (int nt = 0; nt < 8; nt++) {
        int c = nt * 8 + 2 * tq;
        *(__half2*)&Q0[c] = __floats2half2_rn(acc[nt][0] * scale, acc[nt][1] * scale);
        *(__half2*)&Q1[c] = __floats2half2_rn(acc[nt][2] * scale, acc[nt][3] * scale);
    }
}

// ---------------------------------------------------------------------------
// flash16 (R12-proven): 128-row q-tiles, 8 warps, 3-stage KV, occ 1.
// V tile loaded row-major [s][dv] from QKV; B fragments via ldmatrix.trans.
// ---------------------------------------------------------------------------
#define FLQ_BYTES  32768
#define FLSTAGE    24576
#define FL16_SMEM  (FLQ_BYTES + 3 * FLSTAGE)

__global__ __launch_bounds__(256, 1)
void flash16_kernel(const __half* __restrict__ Qc, const __half* __restrict__ Kc,
                    const __half* __restrict__ QKV, __half* __restrict__ O)
{
    extern __shared__ __align__(1024) char smem[];
    uint32_t sbase;
    asm("{ .reg .u64 t; cvta.to.shared.u64 t, %1; cvt.u32.u64 %0, t; }"
        : "=r"(sbase) : "l"(smem));

    int tid  = threadIdx.x;
    int w    = tid >> 5;
    int lane = tid & 31;
    int lm   = lane >> 3;
    int lr   = lane & 7;
    int g    = lane >> 2;
    int tq   = lane & 3;

    int bh    = blockIdx.y;
    int b     = bh >> 4;
    int h     = bh & 15;
    int qtile = (int)gridDim.x - 1 - (int)blockIdx.x;
    int qt0   = qtile * 128;
    int nkt   = 2 * qtile + 2;

    const __half* Qg = Qc + ((size_t)bh * SEQ + qt0) * 128;
#pragma unroll
    for (int i = 0; i < 8; i++) {
        int idx = tid + i * 256;
        int r   = idx >> 4;
        int ch  = idx & 15;
        uint32_t dst = sbase + (uint32_t)(ch >> 3) * 16384
                     + (uint32_t)(r << 7) + ((uint32_t)((ch & 7) ^ (r & 7)) << 4);
        cp16s(dst, Qg + (size_t)r * 128 + ch * 8);
    }
    asm volatile("cp.async.commit_group;");

    auto issueKV = [&](int kt, int s) {
        uint32_t kb = sbase + FLQ_BYTES + (uint32_t)s * FLSTAGE;
        uint32_t vb = kb + 16384;
        const __half* Kg = Kc + ((size_t)bh * SEQ + kt * 64) * 128;
        const __half* Vg = QKV + (size_t)(b * SEQ + kt * 64) * 3072 + 2048 + h * 64;
#pragma unroll
        for (int i = 0; i < 4; i++) {
            int idx = tid + i * 256;
            int r   = idx >> 4;
            int ch  = idx & 15;
            uint32_t dst = kb + (uint32_t)(ch >> 3) * 8192
                         + (uint32_t)(r << 7) + ((uint32_t)((ch & 7) ^ (r & 7)) << 4);
            cp16s(dst, Kg + (size_t)r * 128 + ch * 8);
        }
#pragma unroll
        for (int i = 0; i < 2; i++) {
            int idx = tid + i * 256;
            int r   = idx >> 3;
            int c   = idx & 7;
            uint32_t dst = vb + (uint32_t)(r << 7) + ((uint32_t)(c ^ (r & 7)) << 4);
            cp16s(dst, Vg + (size_t)r * 3072 + c * 8);
        }
        asm volatile("cp.async.commit_group;");
    };

    issueKV(0, 0);
    issueKV(1, 1);

    asm volatile("cp.async.wait_group 2;");
    __syncthreads();

    uint32_t qf[8][4];
#pragma unroll
    for (int ks = 0; ks < 8; ks++) {
        int half = ks >> 2;
        int kc   = (ks & 3) * 2 + (lm >> 1);
        int row  = w * 16 + (lm & 1) * 8 + lr;
        uint32_t ad = sbase + (uint32_t)half * 16384
                    + (uint32_t)(row << 7) + ((uint32_t)(kc ^ (row & 7)) << 4);
        LDSM_X4(qf[ks][0], qf[ks][1], qf[ks][2], qf[ks][3], ad);
    }

    float oacc[8][4];
#pragma unroll
    for (int nt = 0; nt < 8; nt++)
#pragma unroll
        for (int t = 0; t < 4; t++) oacc[nt][t] = 0.f;
    float mrow[2] = {-1e30f, -1e30f};
    float lrow[2] = {0.f, 0.f};

    int qrow0 = qt0 + w * 16;
    int r0g   = qrow0 + g;

    for (int kt = 0; kt < nkt; kt++) {
        int s_ = kt % 3;
        if (kt + 1 < nkt) asm volatile("cp.async.wait_group 1;");
        else              asm volatile("cp.async.wait_group 0;");
        __syncthreads();

        if (kt + 2 < nkt) issueKV(kt + 2, (kt + 2) % 3);

        uint32_t kb = sbase + FLQ_BYTES + (uint32_t)s_ * FLSTAGE;
        uint32_t vb = kb + 16384;

        float sacc[8][4];
#pragma unroll
        for (int nt = 0; nt < 8; nt++)
#pragma unroll
            for (int t = 0; t < 4; t++) sacc[nt][t] = 0.f;

#pragma unroll
        for (int ks = 0; ks < 8; ks++) {
            int half = ks >> 2;
            int kc   = (ks & 3) * 2 + (lm & 1);
            uint32_t kf[8][2];
#pragma unroll
            for (int nb = 0; nb < 4; nb++) {
                int row = nb * 16 + (lm >> 1) * 8 + lr;
                uint32_t ad = kb + (uint32_t)half * 8192
                            + (uint32_t)(row << 7) + ((uint32_t)(kc ^ (row & 7)) << 4);
                LDSM_X4(kf[nb * 2][0], kf[nb * 2][1],
                        kf[nb * 2 + 1][0], kf[nb * 2 + 1][1], ad);
            }
#pragma unroll
            for (int nt = 0; nt < 8; nt++)
                MMA16816H(sacc[nt], qf[ks][0], qf[ks][1], qf[ks][2], qf[ks][3],
                          kf[nt][0], kf[nt][1]);
        }

        if (kt * 64 + 63 > qrow0) {
#pragma unroll
            for (int nt = 0; nt < 8; nt++) {
                int c0 = kt * 64 + nt * 8 + 2 * tq;
                if (c0     > r0g)     sacc[nt][0] = -1e30f;
                if (c0 + 1 > r0g)     sacc[nt][1] = -1e30f;
                if (c0     > r0g + 8) sacc[nt][2] = -1e30f;
                if (c0 + 1 > r0g + 8) sacc[nt][3] = -1e30f;
            }
        }

        float tm0 = -1e30f, tm1 = -1e30f;
#pragma unroll
        for (int nt = 0; nt < 8; nt++) {
            tm0 = fmaxf(tm0, fmaxf(sacc[nt][0], sacc[nt][1]));
            tm1 = fmaxf(tm1, fmaxf(sacc[nt][2], sacc[nt][3]));
        }
        tm0 = fmaxf(tm0, __shfl_xor_sync(0xffffffffu, tm0, 1));
        tm0 = fmaxf(tm0, __shfl_xor_sync(0xffffffffu, tm0, 2));
        tm1 = fmaxf(tm1, __shfl_xor_sync(0xffffffffu, tm1, 1));
        tm1 = fmaxf(tm1, __shfl_xor_sync(0xffffffffu, tm1, 2));

        float mnew0 = fmaxf(mrow[0], tm0);
        float mnew1 = fmaxf(mrow[1], tm1);
        float corr0 = exp2f(mrow[0] - mnew0);
        float corr1 = exp2f(mrow[1] - mnew1);
        mrow[0] = mnew0;
        mrow[1] = mnew1;
#pragma unroll
        for (int nt = 0; nt < 8; nt++) {
            oacc[nt][0] *= corr0; oacc[nt][1] *= corr0;
            oacc[nt][2] *= corr1; oacc[nt][3] *= corr1;
        }

        uint32_t pf[4][4];
        float ps0 = 0.f, ps1 = 0.f;
#pragma unroll
        for (int nt = 0; nt < 8; nt++) {
            __half2 d0 = __floats2half2_rn(sacc[nt][0] - mnew0, sacc[nt][1] - mnew0);
            __half2 d1 = __floats2half2_rn(sacc[nt][2] - mnew1, sacc[nt][3] - mnew1);
            uint32_t p0 = h2exp2(*(uint32_t*)&d0);
            uint32_t p1 = h2exp2(*(uint32_t*)&d1);
            float2 f0 = __half22float2(*(__half2*)&p0);
            float2 f1 = __half22float2(*(__half2*)&p1);
            ps0 += f0.x + f0.y;
            ps1 += f1.x + f1.y;
            pf[nt >> 1][(nt & 1) * 2]     = p0;
            pf[nt >> 1][(nt & 1) * 2 + 1] = p1;
        }
        ps0 += __shfl_xor_sync(0xffffffffu, ps0, 1);
        ps0 += __shfl_xor_sync(0xffffffffu, ps0, 2);
        ps1 += __shfl_xor_sync(0xffffffffu, ps1, 1);
        ps1 += __shfl_xor_sync(0xffffffffu, ps1, 2);
        lrow[0] = lrow[0] * corr0 + ps0;
        lrow[1] = lrow[1] * corr1 + ps1;

        // O += P @ V : V tile [s][dv]; trans-ldmatrix -> B fragments
#pragma unroll
        for (int kc16 = 0; kc16 < 4; kc16++) {
            uint32_t vf[8][2];
#pragma unroll
            for (int nb = 0; nb < 4; nb++) {
                int srow = kc16 * 16 + (lm & 1) * 8 + lr;
                int ch   = nb * 2 + (lm >> 1);
                uint32_t ad = vb + (uint32_t)(srow << 7)
                            + ((uint32_t)(ch ^ (srow & 7)) << 4);
                LDSM_X4_T(vf[nb * 2][0], vf[nb * 2][1],
                          vf[nb * 2 + 1][0], vf[nb * 2 + 1][1], ad);
            }
#pragma unroll
            for (int nt = 0; nt < 8; nt++)
                MMA16816H(oacc[nt], pf[kc16][0], pf[kc16][1], pf[kc16][2], pf[kc16][3],
                          vf[nt][0], vf[nt][1]);
        }
    }

    float inv0 = 1.0f / lrow[0];
    float inv1 = 1.0f / lrow[1];
    size_t rt0 = (size_t)(b * SEQ + qt0 + w * 16 + g);
    __half* O0 = O + rt0 * EMB + h * 64;
    __half* O1 = O0 + (size_t)8 * EMB;
#pragma unroll
    for (int nt = 0; nt < 8; nt++) {
        int c = nt * 8 + 2 * tq;
        *(__half2*)&O0[c] = __floats2half2_rn(oacc[nt][0] * inv0, oacc[nt][1] * inv0);
        *(__half2*)&O1[c] = __floats2half2_rn(oacc[nt][2] * inv1, oacc[nt][3] * inv1);
    }
}

// ---------------------------------------------------------------------------
// launch
// ---------------------------------------------------------------------------
extern "C" void kernel_launch(void* const* d_in, const int* in_sizes, int n_in,
                              void* d_out, int out_size)
{
    const float* x   = (const float*)d_in[0];
    const float* Wq  = (const float*)d_in[1];
    const float* bq  = (const float*)d_in[2];
    const float* Wk  = (const float*)d_in[3];
    const float* bk  = (const float*)d_in[4];
    const float* Wv  = (const float*)d_in[5];
    const float* bv  = (const float*)d_in[6];
    const float* Wo  = (const float*)d_in[7];
    const float* bo  = (const float*)d_in[8];
    const float* J   = (const float*)d_in[9];
    const float* lam = (const float*)d_in[10];
    float* out = (float*)d_out;

    void* p = nullptr;
    cudaGetSymbolAddress(&p, g_hscratch);
    __half* hs    = (__half*)p;
    __half* x16   = hs + HX;
    __half* w16   = hs + HW;
    __half* qkv16 = hs + HQKV;
    __half* qc    = hs + HQC;
    __half* kc    = hs + HKC;
    __half* tq16  = hs + HTQ;
    __half* jt16  = hs + HJT;
    __half* o16   = hs + HO;

    const int WSZ = EMB * EMB;
    __half* wo16 = w16 + 3 * WSZ;

    convert_kernel<<<(N_TOK * EMB / 4 + 255) / 256, 256>>>(x, x16, N_TOK * EMB / 4);
    dim3 tg(32, 32, 4), tb(256);
    transpose4_kernel<<<tg, tb>>>(Wq, Wk, Wv, Wo, w16);
    jt_kernel<<<dim3(2, 2, 16), 256>>>(J, jt16);

    cudaFuncSetAttribute(gemm_fp16, cudaFuncAttributeMaxDynamicSharedMemorySize, GSMEM);
    gemm_fp16<<<dim3(24, 32), 256, GSMEM>>>(x16, w16, bq, bk, bv, qkv16, 3072, 1);

    prep_elem_kernel<<<N_TOK * 512 / 256, 256>>>(qkv16, qc, kc, tq16);
    delta_gemm_kernel<<<dim3(SEQ / 128, BH), 256>>>(tq16, jt16, lam, qc);

    cudaFuncSetAttribute(flash16_kernel, cudaFuncAttributeMaxDynamicSharedMemorySize,
                         FL16_SMEM);
    dim3 fl_grid(SEQ / 128, BH);
    flash16_kernel<<<fl_grid, 256, FL16_SMEM>>>(qc, kc, qkv16, o16);

    gemm_fp16<<<dim3(8, 32), 256, GSMEM>>>(o16, wo16, bo, bo, bo, out, 1024, 0);
}

// round 17
// speedup vs baseline: 1.2953x; 1.0493x over previous
#include <cuda_runtime.h>
#include <cuda_fp16.h>
#include <math.h>
#include <stdint.h>

// ---------------------------------------------------------------------------
// QBNN attention, all-fp16 tensor-core pipeline. B=2, S=2048, E=1024, H=16, hd=64.
//  0) convert: x -> fp16 ; W* -> transposed fp16 ; J -> transposed fp16
//  1) gemm_fp16 fused: QKV = x@[Wq|Wk|Wv] + b  (one launch, N=3072)
//  2) prep_elem + delta_gemm (tensor cores) -> Qcat/Kcat
//  3) flash16: 64-row q-tiles, 4 warps, 3 CTAs/SM, V from QKV (trans ldmatrix)
//  4) gemm_fp16: out = O@Wo + bo (fp32 out)
// ---------------------------------------------------------------------------

#define N_TOK   4096
#define EMB     1024
#define HEADS   16
#define HD      64
#define SEQ     2048
#define BH      32
#define LOG2E   1.4426950408889634f

// fp16 scratch arena
#define HX     0
#define HW     (HX    + N_TOK*EMB)
#define HQKV   (HW    + 4*EMB*EMB)
#define HQC    (HQKV  + N_TOK*3*EMB)
#define HKC    (HQC   + BH*SEQ*128)
#define HTQ    (HKC   + BH*SEQ*128)
#define HJT    (HTQ   + BH*SEQ*64)
#define HO     (HJT   + HEADS*64*64)
#define HTOTAL (HO    + N_TOK*EMB)
__device__ __half g_hscratch[HTOTAL];

// ---------------------------------------------------------------------------
// convert: fp32 -> fp16 elementwise
// ---------------------------------------------------------------------------
__global__ __launch_bounds__(256)
void convert_kernel(const float* __restrict__ src, __half* __restrict__ dst, int n4)
{
    int i = blockIdx.x * blockDim.x + threadIdx.x;
    if (i >= n4) return;
    float4 v = ((const float4*)src)[i];
    __half2 h0 = __floats2half2_rn(v.x, v.y);
    __half2 h1 = __floats2half2_rn(v.z, v.w);
    uint2 w;
    w.x = *(uint32_t*)&h0;
    w.y = *(uint32_t*)&h1;
    ((uint2*)dst)[i] = w;
}

// ---------------------------------------------------------------------------
// fused transpose+convert of all 4 weights: W[k][n] fp32 -> Wt[n][k] fp16
// ---------------------------------------------------------------------------
__global__ __launch_bounds__(256)
void transpose4_kernel(const float* __restrict__ W0, const float* __restrict__ W1,
                       const float* __restrict__ W2, const float* __restrict__ W3,
                       __half* __restrict__ Tbase)
{
    __shared__ float tile[32][33];
    int z  = blockIdx.z;
    const float* W = (z == 0) ? W0 : (z == 1) ? W1 : (z == 2) ? W2 : W3;
    __half* T = Tbase + (size_t)z * EMB * EMB;

    int k0 = blockIdx.y * 32;
    int n0 = blockIdx.x * 32;
    int tx = threadIdx.x & 31;
    int ty = threadIdx.x >> 5;
#pragma unroll
    for (int j = 0; j < 4; j++)
        tile[ty + j * 8][tx] = W[(size_t)(k0 + ty + j * 8) * EMB + n0 + tx];
    __syncthreads();
#pragma unroll
    for (int j = 0; j < 4; j++) {
        int n = ty + j * 8;
        T[(size_t)(n0 + n) * EMB + k0 + tx] = __float2half(tile[tx][n]);
    }
}

// ---------------------------------------------------------------------------
// Jt: J[h][dd][d] fp32 -> Jt[h][d][dd] fp16
// ---------------------------------------------------------------------------
__global__ __launch_bounds__(256)
void jt_kernel(const float* __restrict__ J, __half* __restrict__ Jt)
{
    __shared__ float t[32][33];
    int h   = blockIdx.z;
    int dd0 = blockIdx.y * 32;
    int d0  = blockIdx.x * 32;
    int tx  = threadIdx.x & 31;
    int ty  = threadIdx.x >> 5;
#pragma unroll
    for (int j = 0; j < 4; j++)
        t[ty + j * 8][tx] = J[h * 4096 + (dd0 + ty + j * 8) * 64 + d0 + tx];
    __syncthreads();
#pragma unroll
    for (int j = 0; j < 4; j++) {
        int d = ty + j * 8;
        Jt[h * 4096 + (d0 + d) * 64 + dd0 + tx] = __float2half(t[tx][d]);
    }
}

// ---------------------------------------------------------------------------
// helpers
// ---------------------------------------------------------------------------
#define MMA16816H(d, a0, a1, a2, a3, b0, b1)                                 \
    asm volatile(                                                            \
        "mma.sync.aligned.m16n8k16.row.col.f32.f16.f16.f32 "                 \
        "{%0,%1,%2,%3}, {%4,%5,%6,%7}, {%8,%9}, {%0,%1,%2,%3};"              \
        : "+f"(d[0]), "+f"(d[1]), "+f"(d[2]), "+f"(d[3])                     \
        : "r"(a0), "r"(a1), "r"(a2), "r"(a3), "r"(b0), "r"(b1))

#define LDSM_X4(r0, r1, r2, r3, addr)                                        \
    asm volatile("ldmatrix.sync.aligned.m8n8.x4.shared.b16 {%0,%1,%2,%3}, [%4];" \
        : "=r"(r0), "=r"(r1), "=r"(r2), "=r"(r3) : "r"(addr))

#define LDSM_X4_T(r0, r1, r2, r3, addr)                                      \
    asm volatile("ldmatrix.sync.aligned.m8n8.x4.trans.shared.b16 {%0,%1,%2,%3}, [%4];" \
        : "=r"(r0), "=r"(r1), "=r"(r2), "=r"(r3) : "r"(addr))

__device__ __forceinline__ void cp16s(uint32_t smem_dst, const void* gmem_src)
{
    asm volatile("cp.async.cg.shared.global [%0], [%1], 16;"
                 :: "r"(smem_dst), "l"(gmem_src));
}

__device__ __forceinline__ uint32_t h2exp2(uint32_t x)
{
    uint32_t r;
    asm("ex2.approx.f16x2 %0, %1;" : "=r"(r) : "r"(x));
    return r;
}

__device__ __forceinline__ float tanh_fast(float x)
{
    float r;
    asm("tanh.approx.f32 %0, %1;" : "=f"(r) : "f"(x));
    return r;
}

// ---------------------------------------------------------------------------
// Single-pass fp16 tensor-core GEMM, fused-N capable (R15-proven).
// ---------------------------------------------------------------------------
#define GSTAGE  32768
#define GSMEM   (3 * GSTAGE)

__global__ __launch_bounds__(256, 2)
void gemm_fp16(const __half* __restrict__ A, const __half* __restrict__ Bt,
               const float* __restrict__ b0p, const float* __restrict__ b1p,
               const float* __restrict__ b2p,
               void* __restrict__ Cout, int outN, int half_out)
{
    extern __shared__ __align__(1024) char smem[];
    const int K = 1024;
    uint32_t sbase;
    asm("{ .reg .u64 t; cvta.to.shared.u64 t, %1; cvt.u32.u64 %0, t; }"
        : "=r"(sbase) : "l"(smem));

    int tid  = threadIdx.x;
    int warp = tid >> 5;
    int lane = tid & 31;
    int wm   = warp & 1;
    int wn   = warp >> 1;
    int m0   = blockIdx.y * 128;
    int n0   = blockIdx.x * 128;

    int sec = n0 >> 10;
    const float* bias = (sec == 0) ? b0p : (sec == 1) ? b1p : b2p;
    int nloc = n0 & 1023;

    float acc[4][4][4];
#pragma unroll
    for (int mi = 0; mi < 4; mi++)
#pragma unroll
        for (int nj = 0; nj < 4; nj++)
#pragma unroll
            for (int t = 0; t < 4; t++) acc[mi][nj][t] = 0.f;

    auto issue = [&](int chunk, int stg) {
        int k0 = chunk << 6;
        const __half* Ap = A  + (size_t)m0 * K + k0;
        const __half* Bp = Bt + (size_t)n0 * K + k0;
        uint32_t aBuf = sbase + stg * GSTAGE;
        uint32_t bBuf = aBuf + 16384;
#pragma unroll
        for (int i = 0; i < 4; i++) {
            int idx = tid + i * 256;
            int r   = idx >> 3;
            int c   = idx & 7;
            uint32_t sw = (uint32_t)(r << 7) | ((uint32_t)(c ^ (r & 7)) << 4);
            cp16s(aBuf + sw, Ap + (size_t)r * K + c * 8);
            cp16s(bBuf + sw, Bp + (size_t)r * K + c * 8);
        }
        asm volatile("cp.async.commit_group;");
    };

    issue(0, 0);
    issue(1, 1);

    int lm  = lane >> 3;
    int lr  = lane & 7;

    for (int t = 0; t < 16; t++) {
        int stg = t % 3;
        if (t < 15) asm volatile("cp.async.wait_group 1;");
        else        asm volatile("cp.async.wait_group 0;");
        __syncthreads();

        uint32_t aBuf = sbase + stg * GSTAGE;
        uint32_t bBuf = aBuf + 16384;

#pragma unroll
        for (int kk = 0; kk < 64; kk += 16) {
            int kc = kk >> 3;
            uint32_t af[4][4];
#pragma unroll
            for (int mi = 0; mi < 4; mi++) {
                int row = wm * 64 + mi * 16 + (lm & 1) * 8 + lr;
                int ch  = kc + (lm >> 1);
                uint32_t ad = aBuf + (uint32_t)(row << 7) + ((uint32_t)(ch ^ (row & 7)) << 4);
                LDSM_X4(af[mi][0], af[mi][1], af[mi][2], af[mi][3], ad);
            }
            uint32_t bf_[4][2];
#pragma unroll
            for (int njp = 0; njp < 2; njp++) {
                int row = wn * 32 + njp * 16 + (lm >> 1) * 8 + lr;
                int ch  = kc + (lm & 1);
                uint32_t bd = bBuf + (uint32_t)(row << 7) + ((uint32_t)(ch ^ (row & 7)) << 4);
                LDSM_X4(bf_[njp * 2][0], bf_[njp * 2][1],
                        bf_[njp * 2 + 1][0], bf_[njp * 2 + 1][1], bd);
            }
#pragma unroll
            for (int mi = 0; mi < 4; mi++)
#pragma unroll
                for (int nj = 0; nj < 4; nj++)
                    MMA16816H(acc[mi][nj], af[mi][0], af[mi][1], af[mi][2], af[mi][3],
                              bf_[nj][0], bf_[nj][1]);
        }

        if (t + 2 < 16) issue(t + 2, (t + 2) % 3);
    }

    int g  = lane >> 2;
    int tq = lane & 3;
#pragma unroll
    for (int mi = 0; mi < 4; mi++) {
        size_t r0 = (size_t)(m0 + wm * 64 + mi * 16 + g);
        size_t r1 = r0 + 8;
#pragma unroll
        for (int nj = 0; nj < 4; nj++) {
            int cl = wn * 32 + nj * 8 + tq * 2;
            float b0 = bias[nloc + cl], b1 = bias[nloc + cl + 1];
            int c  = n0 + cl;
            float v00 = acc[mi][nj][0] + b0, v01 = acc[mi][nj][1] + b1;
            float v10 = acc[mi][nj][2] + b0, v11 = acc[mi][nj][3] + b1;
            if (half_out) {
                __half* C = (__half*)Cout;
                *(__half2*)&C[r0 * outN + c] = __floats2half2_rn(v00, v01);
                *(__half2*)&C[r1 * outN + c] = __floats2half2_rn(v10, v11);
            } else {
                float* C = (float*)Cout;
                *(float2*)&C[r0 * outN + c] = make_float2(v00, v01);
                *(float2*)&C[r1 * outN + c] = make_float2(v10, v11);
            }
        }
    }
}

// ---------------------------------------------------------------------------
// prep_elem: pure elementwise pass (half2). Writes Qc[0:64], Kc, tQ.
// ---------------------------------------------------------------------------
__global__ __launch_bounds__(256)
void prep_elem_kernel(const __half* __restrict__ QKV,
                      __half* __restrict__ Qc, __half* __restrict__ Kc,
                      __half* __restrict__ tQ)
{
    int idx = blockIdx.x * 256 + threadIdx.x;
    int tok = idx >> 9;
    int e2  = idx & 511;
    int e   = e2 << 1;
    int h   = e >> 6;
    int d   = e & 63;
    int b   = tok >> 11;
    int s   = tok & 2047;
    int bh  = (b << 4) + h;

    const __half2* row = (const __half2*)(QKV + (size_t)tok * 3072);
    float2 q = __half22float2(row[e2]);
    __half2 kh = row[512 + e2];
    float2 k = __half22float2(kh);

    size_t base = ((size_t)bh * SEQ + s) * 128;
    *(__half2*)&Qc[base + d] =
        __floats2half2_rn(q.x * 0.125f * LOG2E, q.y * 0.125f * LOG2E);
    *(__half2*)&Kc[base + d] = kh;
    *(__half2*)&Kc[base + 64 + d] =
        __floats2half2_rn(tanh_fast(k.x), tanh_fast(k.y));
    *(__half2*)&tQ[((size_t)bh * SEQ + s) * 64 + d] =
        __floats2half2_rn(tanh_fast(q.x), tanh_fast(q.y));
}

// ---------------------------------------------------------------------------
// delta_gemm: Qc[.., 64:128] = lam*log2e * (tQ @ J) per (bh, 128-row tile).
// ---------------------------------------------------------------------------
__global__ __launch_bounds__(256)
void delta_gemm_kernel(const __half* __restrict__ tQ, const __half* __restrict__ Jt,
                       const float* __restrict__ lamp, __half* __restrict__ Qc)
{
    __shared__ __align__(1024) __half sA[128 * 64];
    __shared__ __align__(1024) __half sB[64 * 64];

    uint32_t aBuf, bBuf;
    asm("{ .reg .u64 t; cvta.to.shared.u64 t, %1; cvt.u32.u64 %0, t; }"
        : "=r"(aBuf) : "l"(sA));
    asm("{ .reg .u64 t; cvta.to.shared.u64 t, %1; cvt.u32.u64 %0, t; }"
        : "=r"(bBuf) : "l"(sB));

    int tid  = threadIdx.x;
    int w    = tid >> 5;
    int lane = tid & 31;
    int lm   = lane >> 3;
    int lr   = lane & 7;
    int g    = lane >> 2;
    int tq   = lane & 3;

    int bh  = blockIdx.y;
    int h   = bh & 15;
    int qt0 = blockIdx.x * 128;

    const __half* Ag = tQ + ((size_t)bh * SEQ + qt0) * 64;
    const __half* Bg = Jt + (size_t)h * 4096;

#pragma unroll
    for (int i = 0; i < 4; i++) {
        int idx = tid + i * 256;
        int r   = idx >> 3;
        int c   = idx & 7;
        uint32_t dst = aBuf + (uint32_t)(r << 7) + ((uint32_t)(c ^ (r & 7)) << 4);
        cp16s(dst, Ag + (size_t)r * 64 + c * 8);
    }
#pragma unroll
    for (int i = 0; i < 2; i++) {
        int idx = tid + i * 256;
        int r   = idx >> 3;
        int c   = idx & 7;
        uint32_t dst = bBuf + (uint32_t)(r << 7) + ((uint32_t)(c ^ (r & 7)) << 4);
        cp16s(dst, Bg + (size_t)r * 64 + c * 8);
    }
    asm volatile("cp.async.commit_group;");
    asm volatile("cp.async.wait_group 0;");
    __syncthreads();

    float acc[8][4];
#pragma unroll
    for (int nt = 0; nt < 8; nt++)
#pragma unroll
        for (int t = 0; t < 4; t++) acc[nt][t] = 0.f;

#pragma unroll
    for (int ks = 0; ks < 4; ks++) {
        int arow = w * 16 + (lm & 1) * 8 + lr;
        int ach  = ks * 2 + (lm >> 1);
        uint32_t aad = aBuf + (uint32_t)(arow << 7) + ((uint32_t)(ach ^ (arow & 7)) << 4);
        uint32_t a0, a1, a2, a3;
        LDSM_X4(a0, a1, a2, a3, aad);

        int bch = ks * 2 + (lm & 1);
        uint32_t bf_[8][2];
#pragma unroll
        for (int nb = 0; nb < 4; nb++) {
            int brow = nb * 16 + (lm >> 1) * 8 + lr;
            uint32_t bad = bBuf + (uint32_t)(brow << 7) + ((uint32_t)(bch ^ (brow & 7)) << 4);
            LDSM_X4(bf_[nb * 2][0], bf_[nb * 2][1],
                    bf_[nb * 2 + 1][0], bf_[nb * 2 + 1][1], bad);
        }
#pragma unroll
        for (int nt = 0; nt < 8; nt++)
            MMA16816H(acc[nt], a0, a1, a2, a3, bf_[nt][0], bf_[nt][1]);
    }

    float scale = lamp[0] * LOG2E;
    size_t r0 = (size_t)bh * SEQ + qt0 + w * 16 + g;
    __half* Q0 = Qc + r0 * 128 + 64;
    __half* Q1 = Q0 + (size_t)8 * 128;
#pragma unroll
    for (int nt = 0; nt < 8; nt++) {
        int c = nt * 8 + 2 * tq;
        *(__half2*)&Q0[c] = __floats2half2_rn(acc[nt][0] * scale, acc[nt][1] * scale);
        *(__half2*)&Q1[c] = __floats2half2_rn(acc[nt][2] * scale, acc[nt][3] * scale);
    }
}

// ---------------------------------------------------------------------------
// flash16: 64-row q-tiles, 4 warps (128 thr), 2-stage KV, 3 CTAs/SM.
// Q fragments hoisted; V tile [s][dv] from QKV via trans-ldmatrix.
// smem: Q 16KB + 2 x 24KB = 64KB.
// ---------------------------------------------------------------------------
#define FLQ_BYTES  16384
#define FLSTAGE    24576
#define FL16_SMEM  (FLQ_BYTES + 2 * FLSTAGE)

__global__ __launch_bounds__(128, 3)
void flash16_kernel(const __half* __restrict__ Qc, const __half* __restrict__ Kc,
                    const __half* __restrict__ QKV, __half* __restrict__ O)
{
    extern __shared__ __align__(1024) char smem[];
    uint32_t sbase;
    asm("{ .reg .u64 t; cvta.to.shared.u64 t, %1; cvt.u32.u64 %0, t; }"
        : "=r"(sbase) : "l"(smem));

    int tid  = threadIdx.x;
    int w    = tid >> 5;              // 0..3
    int lane = tid & 31;
    int lm   = lane >> 3;
    int lr   = lane & 7;
    int g    = lane >> 2;
    int tq   = lane & 3;

    int bh    = blockIdx.y;
    int b     = bh >> 4;
    int h     = bh & 15;
    int qtile = (int)gridDim.x - 1 - (int)blockIdx.x;   // heavy first
    int qt0   = qtile * 64;
    int nkt   = qtile + 1;

    // Q load: 64 rows x 16 chunks = 1024 over 128 threads
    const __half* Qg = Qc + ((size_t)bh * SEQ + qt0) * 128;
#pragma unroll
    for (int i = 0; i < 8; i++) {
        int idx = tid + i * 128;
        int r   = idx >> 4;
        int ch  = idx & 15;
        uint32_t dst = sbase + (uint32_t)(ch >> 3) * 8192
                     + (uint32_t)(r << 7) + ((uint32_t)((ch & 7) ^ (r & 7)) << 4);
        cp16s(dst, Qg + (size_t)r * 128 + ch * 8);
    }
    asm volatile("cp.async.commit_group;");

    auto issueKV = [&](int kt, int s) {
        uint32_t kb = sbase + FLQ_BYTES + (uint32_t)s * FLSTAGE;
        uint32_t vb = kb + 16384;
        const __half* Kg = Kc + ((size_t)bh * SEQ + kt * 64) * 128;
        const __half* Vg = QKV + (size_t)(b * SEQ + kt * 64) * 3072 + 2048 + h * 64;
#pragma unroll
        for (int i = 0; i < 8; i++) {
            int idx = tid + i * 128;
            int r   = idx >> 4;
            int ch  = idx & 15;
            uint32_t dst = kb + (uint32_t)(ch >> 3) * 8192
                         + (uint32_t)(r << 7) + ((uint32_t)((ch & 7) ^ (r & 7)) << 4);
            cp16s(dst, Kg + (size_t)r * 128 + ch * 8);
        }
#pragma unroll
        for (int i = 0; i < 4; i++) {
            int idx = tid + i * 128;
            int r   = idx >> 3;
            int c   = idx & 7;
            uint32_t dst = vb + (uint32_t)(r << 7) + ((uint32_t)(c ^ (r & 7)) << 4);
            cp16s(dst, Vg + (size_t)r * 3072 + c * 8);
        }
        asm volatile("cp.async.commit_group;");
    };

    issueKV(0, 0);
    if (nkt > 1) issueKV(1, 1);
    else         asm volatile("cp.async.commit_group;");   // keep group count fixed

    asm volatile("cp.async.wait_group 2;");
    __syncthreads();

    uint32_t qf[8][4];
#pragma unroll
    for (int ks = 0; ks < 8; ks++) {
        int half = ks >> 2;
        int kc   = (ks & 3) * 2 + (lm >> 1);
        int row  = w * 16 + (lm & 1) * 8 + lr;
        uint32_t ad = sbase + (uint32_t)half * 8192
                    + (uint32_t)(row << 7) + ((uint32_t)(kc ^ (row & 7)) << 4);
        LDSM_X4(qf[ks][0], qf[ks][1], qf[ks][2], qf[ks][3], ad);
    }

    float oacc[8][4];
#pragma unroll
    for (int nt = 0; nt < 8; nt++)
#pragma unroll
        for (int t = 0; t < 4; t++) oacc[nt][t] = 0.f;
    float mrow[2] = {-1e30f, -1e30f};
    float lrow[2] = {0.f, 0.f};

    int qrow0 = qt0 + w * 16;
    int r0g   = qrow0 + g;

    for (int kt = 0; kt < nkt; kt++) {
        int s_ = kt & 1;
        if (kt + 1 < nkt) asm volatile("cp.async.wait_group 1;");
        else              asm volatile("cp.async.wait_group 0;");
        __syncthreads();

        uint32_t kb = sbase + FLQ_BYTES + (uint32_t)s_ * FLSTAGE;
        uint32_t vb = kb + 16384;

        float sacc[8][4];
#pragma unroll
        for (int nt = 0; nt < 8; nt++)
#pragma unroll
            for (int t = 0; t < 4; t++) sacc[nt][t] = 0.f;

#pragma unroll
        for (int ks = 0; ks < 8; ks++) {
            int half = ks >> 2;
            int kc   = (ks & 3) * 2 + (lm & 1);
            uint32_t kf[8][2];
#pragma unroll
            for (int nb = 0; nb < 4; nb++) {
                int row = nb * 16 + (lm >> 1) * 8 + lr;
                uint32_t ad = kb + (uint32_t)half * 8192
                            + (uint32_t)(row << 7) + ((uint32_t)(kc ^ (row & 7)) << 4);
                LDSM_X4(kf[nb * 2][0], kf[nb * 2][1],
                        kf[nb * 2 + 1][0], kf[nb * 2 + 1][1], ad);
            }
#pragma unroll
            for (int nt = 0; nt < 8; nt++)
                MMA16816H(sacc[nt], qf[ks][0], qf[ks][1], qf[ks][2], qf[ks][3],
                          kf[nt][0], kf[nt][1]);
        }

        if (kt * 64 + 63 > qrow0) {
#pragma unroll
            for (int nt = 0; nt < 8; nt++) {
                int c0 = kt * 64 + nt * 8 + 2 * tq;
                if (c0     > r0g)     sacc[nt][0] = -1e30f;
                if (c0 + 1 > r0g)     sacc[nt][1] = -1e30f;
                if (c0     > r0g + 8) sacc[nt][2] = -1e30f;
                if (c0 + 1 > r0g + 8) sacc[nt][3] = -1e30f;
            }
        }

        float tm0 = -1e30f, tm1 = -1e30f;
#pragma unroll
        for (int nt = 0; nt < 8; nt++) {
            tm0 = fmaxf(tm0, fmaxf(sacc[nt][0], sacc[nt][1]));
            tm1 = fmaxf(tm1, fmaxf(sacc[nt][2], sacc[nt][3]));
        }
        tm0 = fmaxf(tm0, __shfl_xor_sync(0xffffffffu, tm0, 1));
        tm0 = fmaxf(tm0, __shfl_xor_sync(0xffffffffu, tm0, 2));
        tm1 = fmaxf(tm1, __shfl_xor_sync(0xffffffffu, tm1, 1));
        tm1 = fmaxf(tm1, __shfl_xor_sync(0xffffffffu, tm1, 2));

        float mnew0 = fmaxf(mrow[0], tm0);
        float mnew1 = fmaxf(mrow[1], tm1);
        float corr0 = exp2f(mrow[0] - mnew0);
        float corr1 = exp2f(mrow[1] - mnew1);
        mrow[0] = mnew0;
        mrow[1] = mnew1;
#pragma unroll
        for (int nt = 0; nt < 8; nt++) {
            oacc[nt][0] *= corr0; oacc[nt][1] *= corr0;
            oacc[nt][2] *= corr1; oacc[nt][3] *= corr1;
        }

        uint32_t pf[4][4];
        float ps0 = 0.f, ps1 = 0.f;
#pragma unroll
        for (int nt = 0; nt < 8; nt++) {
            __half2 d0 = __floats2half2_rn(sacc[nt][0] - mnew0, sacc[nt][1] - mnew0);
            __half2 d1 = __floats2half2_rn(sacc[nt][2] - mnew1, sacc[nt][3] - mnew1);
            uint32_t p0 = h2exp2(*(uint32_t*)&d0);
            uint32_t p1 = h2exp2(*(uint32_t*)&d1);
            float2 f0 = __half22float2(*(__half2*)&p0);
            float2 f1 = __half22float2(*(__half2*)&p1);
            ps0 += f0.x + f0.y;
            ps1 += f1.x + f1.y;
            pf[nt >> 1][(nt & 1) * 2]     = p0;
            pf[nt >> 1][(nt & 1) * 2 + 1] = p1;
        }
        ps0 += __shfl_xor_sync(0xffffffffu, ps0, 1);
        ps0 += __shfl_xor_sync(0xffffffffu, ps0, 2);
        ps1 += __shfl_xor_sync(0xffffffffu, ps1, 1);
        ps1 += __shfl_xor_sync(0xffffffffu, ps1, 2);
        lrow[0] = lrow[0] * corr0 + ps0;
        lrow[1] = lrow[1] * corr1 + ps1;

        // O += P @ V : V tile [s][dv]; trans-ldmatrix -> B fragments
#pragma unroll
        for (int kc16 = 0; kc16 < 4; kc16++) {
            uint32_t vf[8][2];
#pragma unroll
            for (int nb = 0; nb < 4; nb++) {
                int srow = kc16 * 16 + (lm & 1) * 8 + lr;
                int ch   = nb * 2 + (lm >> 1);
                uint32_t ad = vb + (uint32_t)(srow << 7)
                            + ((uint32_t)(ch ^ (srow & 7)) << 4);
                LDSM_X4_T(vf[nb * 2][0], vf[nb * 2][1],
                          vf[nb * 2 + 1][0], vf[nb * 2 + 1][1], ad);
            }
#pragma unroll
            for (int nt = 0; nt < 8; nt++)
                MMA16816H(oacc[nt], pf[kc16][0], pf[kc16][1], pf[kc16][2], pf[kc16][3],
                          vf[nt][0], vf[nt][1]);
        }

        __syncthreads();
        if (kt + 2 < nkt) issueKV(kt + 2, s_);
    }

    float inv0 = 1.0f / lrow[0];
    float inv1 = 1.0f / lrow[1];
    size_t rt0 = (size_t)(b * SEQ + qt0 + w * 16 + g);
    __half* O0 = O + rt0 * EMB + h * 64;
    __half* O1 = O0 + (size_t)8 * EMB;
#pragma unroll
    for (int nt = 0; nt < 8; nt++) {
        int c = nt * 8 + 2 * tq;
        *(__half2*)&O0[c] = __floats2half2_rn(oacc[nt][0] * inv0, oacc[nt][1] * inv0);
        *(__half2*)&O1[c] = __floats2half2_rn(oacc[nt][2] * inv1, oacc[nt][3] * inv1);
    }
}

// ---------------------------------------------------------------------------
// launch
// ---------------------------------------------------------------------------
extern "C" void kernel_launch(void* const* d_in, const int* in_sizes, int n_in,
                              void* d_out, int out_size)
{
    const float* x   = (const float*)d_in[0];
    const float* Wq  = (const float*)d_in[1];
    const float* bq  = (const float*)d_in[2];
    const float* Wk  = (const float*)d_in[3];
    const float* bk  = (const float*)d_in[4];
    const float* Wv  = (const float*)d_in[5];
    const float* bv  = (const float*)d_in[6];
    const float* Wo  = (const float*)d_in[7];
    const float* bo  = (const float*)d_in[8];
    const float* J   = (const float*)d_in[9];
    const float* lam = (const float*)d_in[10];
    float* out = (float*)d_out;

    void* p = nullptr;
    cudaGetSymbolAddress(&p, g_hscratch);
    __half* hs    = (__half*)p;
    __half* x16   = hs + HX;
    __half* w16   = hs + HW;
    __half* qkv16 = hs + HQKV;
    __half* qc    = hs + HQC;
    __half* kc    = hs + HKC;
    __half* tq16  = hs + HTQ;
    __half* jt16  = hs + HJT;
    __half* o16   = hs + HO;

    const int WSZ = EMB * EMB;
    __half* wo16 = w16 + 3 * WSZ;

    convert_kernel<<<(N_TOK * EMB / 4 + 255) / 256, 256>>>(x, x16, N_TOK * EMB / 4);
    dim3 tg(32, 32, 4), tb(256);
    transpose4_kernel<<<tg, tb>>>(Wq, Wk, Wv, Wo, w16);
    jt_kernel<<<dim3(2, 2, 16), 256>>>(J, jt16);

    cudaFuncSetAttribute(gemm_fp16, cudaFuncAttributeMaxDynamicSharedMemorySize, GSMEM);
    gemm_fp16<<<dim3(24, 32), 256, GSMEM>>>(x16, w16, bq, bk, bv, qkv16, 3072, 1);

    prep_elem_kernel<<<N_TOK * 512 / 256, 256>>>(qkv16, qc, kc, tq16);
    delta_gemm_kernel<<<dim3(SEQ / 128, BH), 256>>>(tq16, jt16, lam, qc);

    cudaFuncSetAttribute(flash16_kernel, cudaFuncAttributeMaxDynamicSharedMemorySize,
                         FL16_SMEM);
    dim3 fl_grid(SEQ / 64, BH);
    flash16_kernel<<<fl_grid, 128, FL16_SMEM>>>(qc, kc, qkv16, o16);

    gemm_fp16<<<dim3(8, 32), 256, GSMEM>>>(o16, wo16, bo, bo, bo, out, 1024, 0);
}